// round 7
// baseline (speedup 1.0000x reference)
#include <cuda_runtime.h>
#include <cuda_bf16.h>

#define N_NODES 100000
#define IN_F 64
#define E_MAX 1600000

// Scratch
__device__ int g_deg[N_NODES];
__device__ int g_off[N_NODES];
__device__ int g_cursor[N_NODES];
__device__ int g_eidx[E_MAX];
__device__ int g_partials[512];
__device__ float g_y[(size_t)N_NODES * 64];   // y = x @ W_lin^T (25.6MB)

// Grid-barrier state (sense-reversing; replay-safe: cnt returns to 0, gen grows)
__device__ int g_bar_cnt[2];
__device__ volatile int g_bar_gen[2];

__device__ __forceinline__ void grid_bar(int id, int nb) {
    __threadfence();
    __syncthreads();
    if (threadIdx.x == 0) {
        int gen = g_bar_gen[id];
        if (atomicAdd(&g_bar_cnt[id], 1) == nb - 1) {
            g_bar_cnt[id] = 0;
            __threadfence();
            g_bar_gen[id] = gen + 1;
        } else {
            while (g_bar_gen[id] == gen) __nanosleep(64);
        }
    }
    __syncthreads();
}

// ---------------------------------------------------------------------------
// Packed f32x2 FMA (Blackwell FFMA2 — PTX only)
// ---------------------------------------------------------------------------
__device__ __forceinline__ unsigned long long fma_f32x2(unsigned long long a,
                                                        unsigned long long b,
                                                        unsigned long long c) {
    unsigned long long d;
    asm("fma.rn.f32x2 %0, %1, %2, %3;" : "=l"(d) : "l"(a), "l"(b), "l"(c));
    return d;
}
__device__ __forceinline__ unsigned long long pack_f32x2(float lo, float hi) {
    unsigned long long r;
    asm("mov.b64 %0, {%1, %2};" : "=l"(r) : "f"(lo), "f"(hi));
    return r;
}
__device__ __forceinline__ float sum_f32x2(unsigned long long v) {
    float lo, hi;
    asm("mov.b64 {%0, %1}, %2;" : "=f"(lo), "=f"(hi) : "l"(v));
    return lo + hi;
}

// ---------------------------------------------------------------------------
// Mega-kernel. Roles by bid%3: {0,1} -> GEMM (y = x@Wl^T, out = x@Ws^T + b),
// {2} -> CSR build. Then all blocks: out[n] += sum_{e:dst=n} y[src[e]].
// ---------------------------------------------------------------------------
__global__ void __launch_bounds__(256, 3)
mega_kernel(const float* __restrict__ x,
            const int* __restrict__ src,
            const int* __restrict__ dst,
            const float* __restrict__ W_lin,
            const float* __restrict__ b_lin,
            const float* __restrict__ W_self,
            const float* __restrict__ b_self,
            const float* __restrict__ bias,
            float* __restrict__ out,
            int N, int E, int nseg, int ntiles, int nchunks) {
    __shared__ float sWl[64 * 64];   // GEMM: [f4][o][4]; CSR aliases as int bufs
    __shared__ float sWs[64 * 64];

    const int t = threadIdx.x;
    const int bid = blockIdx.x;
    const int grid = gridDim.x;
    const int nCSR = grid / 3;
    const int nGEMM = grid - nCSR;
    const int r3 = bid % 3;
    const int q3 = bid / 3;

    if (r3 == 2) {
        // ================= CSR role (nCSR blocks, index ci) =================
        int ci = q3;
        int* ib0 = (int*)sWl;          // 512 ints
        int* ib1 = (int*)sWl + 512;

        // zero degrees
        for (int i = ci * 256 + t; i < N; i += nCSR * 256) g_deg[i] = 0;
        grid_bar(0, nCSR);

        // count in-degrees
        for (int e = ci * 256 + t; e < E; e += nCSR * 256) {
            int* p = &g_deg[__ldg(dst + e)];
            asm volatile("red.global.add.s32 [%0], 1;" :: "l"(p) : "memory");
        }
        grid_bar(0, nCSR);

        // per-segment (256-wide) block scans
        for (int s = ci; s < nseg; s += nCSR) {
            int i = s * 256 + t;
            int v = (i < N) ? g_deg[i] : 0;
            ib0[t] = v;
            __syncthreads();
            int* a = ib0; int* b = ib1;
            #pragma unroll
            for (int off = 1; off < 256; off <<= 1) {
                int sv = a[t];
                if (t >= off) sv += a[t - off];
                b[t] = sv;
                __syncthreads();
                int* tmp = a; a = b; b = tmp;
            }
            if (t == 255) g_partials[s] = a[255];
            if (i < N) g_off[i] = a[t] - v;   // exclusive within segment
            __syncthreads();
        }
        grid_bar(0, nCSR);

        // block ci==0: exclusive scan of nseg partials (nseg <= 512)
        if (ci == 0) {
            int v0 = (t < nseg) ? g_partials[t] : 0;
            int v1 = (t + 256 < nseg) ? g_partials[t + 256] : 0;
            ib0[t] = v0; ib0[t + 256] = v1;
            __syncthreads();
            int* a = ib0; int* b = ib1;
            #pragma unroll
            for (int off = 1; off < 512; off <<= 1) {
                int s0 = a[t];
                if (t >= off) s0 += a[t - off];
                int s1 = a[t + 256] + a[t + 256 - off];
                b[t] = s0; b[t + 256] = s1;
                __syncthreads();
                int* tmp = a; a = b; b = tmp;
            }
            if (t < nseg) g_partials[t] = a[t] - v0;
            if (t + 256 < nseg) g_partials[t + 256] = a[t + 256] - v1;
        }
        grid_bar(0, nCSR);

        // add segment bases; init cursors
        for (int s = ci; s < nseg; s += nCSR) {
            int base = g_partials[s];
            int i = s * 256 + t;
            if (i < N) {
                int sv = g_off[i] + base;
                g_off[i] = sv;
                g_cursor[i] = sv;
            }
        }
        grid_bar(0, nCSR);

        // fill buckets
        for (int e = ci * 256 + t; e < E; e += nCSR * 256) {
            int d = __ldg(dst + e);
            int pos = atomicAdd(&g_cursor[d], 1);
            g_eidx[pos] = __ldg(src + e);
        }
    } else {
        // ================= GEMM role (nGEMM blocks, index gi) ===============
        int gi = q3 * 2 + r3;

        // weights transposed into smem: [f4][o][4]
        #pragma unroll
        for (int i = t; i < 64 * 64; i += 256) {
            int o = i >> 6;
            int f = i & 63;
            int dsti = (f >> 2) * 256 + o * 4 + (f & 3);
            sWl[dsti] = W_lin[i];
            sWs[dsti] = W_self[i];
        }
        __syncthreads();

        int o = t & 63;
        int g = t >> 6;           // 0..3
        float b = b_lin[o] + b_self[o] + bias[o];

        for (int tile = gi; tile < ntiles; tile += nGEMM) {
            int n0 = tile * 32 + g * 8;
            const float* __restrict__ xbase = x + (size_t)n0 * 64;

            if (n0 + 7 < N) {
                unsigned long long accY[8], accS[8];
                unsigned long long binit = pack_f32x2(b, 0.f);
                #pragma unroll
                for (int k = 0; k < 8; k++) { accY[k] = 0ull; accS[k] = binit; }

                #pragma unroll
                for (int f4 = 0; f4 < 16; f4++) {
                    ulonglong2 wl = *reinterpret_cast<const ulonglong2*>(
                                        &sWl[f4 * 256 + o * 4]);
                    ulonglong2 ws = *reinterpret_cast<const ulonglong2*>(
                                        &sWs[f4 * 256 + o * 4]);
                    #pragma unroll
                    for (int k = 0; k < 8; k++) {
                        ulonglong2 xv = *reinterpret_cast<const ulonglong2*>(
                                            xbase + k * 64 + f4 * 4);
                        accY[k] = fma_f32x2(xv.x, wl.x, accY[k]);
                        accY[k] = fma_f32x2(xv.y, wl.y, accY[k]);
                        accS[k] = fma_f32x2(xv.x, ws.x, accS[k]);
                        accS[k] = fma_f32x2(xv.y, ws.y, accS[k]);
                    }
                }
                float* yp = g_y + (size_t)n0 * 64 + o;
                float* op = out + (size_t)n0 * 64 + o;
                #pragma unroll
                for (int k = 0; k < 8; k++) {
                    yp[k * 64] = sum_f32x2(accY[k]);
                    op[k * 64] = sum_f32x2(accS[k]);
                }
            } else {
                for (int k = 0; k < 8; k++) {
                    int n = n0 + k;
                    if (n >= N) break;
                    float ay = 0.f, as = b;
                    for (int f = 0; f < 64; f++) {
                        float xv = xbase[k * 64 + f];
                        ay += xv * sWl[(f >> 2) * 256 + o * 4 + (f & 3)];
                        as += xv * sWs[(f >> 2) * 256 + o * 4 + (f & 3)];
                    }
                    g_y[(size_t)n * 64 + o] = ay;
                    out[(size_t)n * 64 + o] = as;
                }
            }
        }
    }

    // ======== join: CSR + GEMM results both ready ========
    grid_bar(1, grid);

    // ================= Gather phase (all blocks) =================
    // out[n] += sum_{e: dst[e]=n} y[src[e]];  16 threads per node.
    const float4* __restrict__ y4 = (const float4*)g_y;
    float4* __restrict__ out4 = (float4*)out;
    int nl = t >> 4;
    int l = t & 15;

    for (int chunk = bid; chunk < nchunks; chunk += grid) {
        int node = chunk * 16 + nl;
        if (node >= N) continue;

        int beg = g_off[node];
        int cnt = g_deg[node];

        float4 a0 = make_float4(0.f, 0.f, 0.f, 0.f);
        float4 a1 = a0, a2 = a0, a3 = a0;

        int j = 0;
        for (; j + 4 <= cnt; j += 4) {
            int s0 = __ldg(g_eidx + beg + j + 0);
            int s1 = __ldg(g_eidx + beg + j + 1);
            int s2 = __ldg(g_eidx + beg + j + 2);
            int s3 = __ldg(g_eidx + beg + j + 3);
            float4 v0 = __ldg(y4 + (size_t)s0 * 16 + l);
            float4 v1 = __ldg(y4 + (size_t)s1 * 16 + l);
            float4 v2 = __ldg(y4 + (size_t)s2 * 16 + l);
            float4 v3 = __ldg(y4 + (size_t)s3 * 16 + l);
            a0.x += v0.x; a0.y += v0.y; a0.z += v0.z; a0.w += v0.w;
            a1.x += v1.x; a1.y += v1.y; a1.z += v1.z; a1.w += v1.w;
            a2.x += v2.x; a2.y += v2.y; a2.z += v2.z; a2.w += v2.w;
            a3.x += v3.x; a3.y += v3.y; a3.z += v3.z; a3.w += v3.w;
        }
        for (; j < cnt; j++) {
            int s = __ldg(g_eidx + beg + j);
            float4 v = __ldg(y4 + (size_t)s * 16 + l);
            a0.x += v.x; a0.y += v.y; a0.z += v.z; a0.w += v.w;
        }

        float4 acc;
        acc.x = (a0.x + a1.x) + (a2.x + a3.x);
        acc.y = (a0.y + a1.y) + (a2.y + a3.y);
        acc.z = (a0.z + a1.z) + (a2.z + a3.z);
        acc.w = (a0.w + a1.w) + (a2.w + a3.w);

        float4 cur = out4[(size_t)node * 16 + l];
        cur.x += acc.x; cur.y += acc.y; cur.z += acc.z; cur.w += acc.w;
        out4[(size_t)node * 16 + l] = cur;
    }
}

// ---------------------------------------------------------------------------
// Launch. Input order: x, src, dst, W_lin, b_lin, W_self, b_self, bias
// ---------------------------------------------------------------------------
extern "C" void kernel_launch(void* const* d_in, const int* in_sizes, int n_in,
                              void* d_out, int out_size) {
    const float* x      = (const float*)d_in[0];
    const int*   src    = (const int*)d_in[1];
    const int*   dst    = (const int*)d_in[2];
    const float* W_lin  = (const float*)d_in[3];
    const float* b_lin  = (const float*)d_in[4];
    const float* W_self = (const float*)d_in[5];
    const float* b_self = (const float*)d_in[6];
    const float* bias   = (const float*)d_in[7];
    float* out = (float*)d_out;

    int N = in_sizes[0] / IN_F;   // 100000
    int E = in_sizes[1];          // 1280000

    int nseg = (N + 255) / 256;           // 391 (<=512 required)
    int ntiles = (N + 31) / 32;           // 3125
    int nchunks = (N + 15) / 16;          // 6250

    // Deadlock-safe persistent grid: exactly the co-resident capacity.
    int dev = 0, sms = 148, occ = 3;
    cudaGetDevice(&dev);
    cudaDeviceGetAttribute(&sms, cudaDevAttrMultiProcessorCount, dev);
    cudaOccupancyMaxActiveBlocksPerMultiprocessor(&occ, mega_kernel, 256, 0);
    int grid = sms * occ;
    if (grid > 444) grid = 444;
    if (grid < 3) grid = 3;

    mega_kernel<<<grid, 256>>>(x, src, dst, W_lin, b_lin, W_self, b_self,
                               bias, out, N, E, nseg, ntiles, nchunks);
}